// round 6
// baseline (speedup 1.0000x reference)
#include <cuda_runtime.h>
#include <cstdint>

// EvalBspPrimeTF: derivative of Bernstein basis, order 16, 4M points -> [4M,17] f32.
// Telescoping form: U_m = 16*C(15,m)*y^m*(1-y)^(15-m), m=0..15
//   out[0] = -U_0;  out[m] = U_{m-1} - U_m (1<=m<=15);  out[16] = U_15
// Reference NaN->0: at y==0, out[0]=out[1]=0; at y==1, out[15]=out[16]=0.
//
// R6: R5 (TPB=128, one 8704B TMA bulk store per CTA) +
//  (a) prefetch.global.L2 of the x-slice ~1 wave of CTAs ahead (decouple DRAM
//      reads from the write stream), and
//  (b) evict_first L2 cache hint on the bulk store (drain written lines fast).

#define TPB   128
#define NCOL  17
#define TILE_WORDS (TPB * NCOL)          // 2176 floats
#define TILE_BYTES (TILE_WORDS * 4)      // 8704 B, multiple of 16
#define AHEAD 2368                        // ~148 SMs * 16 resident CTAs

__device__ __forceinline__ void compute_point(float y, float* __restrict__ o)
{
    // 16*C(15,m)
    const float K[16] = {
        16.f, 240.f, 1680.f, 7280.f, 21840.f, 48048.f, 80080.f, 102960.f,
        102960.f, 80080.f, 48048.f, 21840.f, 7280.f, 1680.f, 240.f, 16.f
    };
    float q = 1.0f - y;

    float yp[16], qp[16];
    yp[0] = 1.0f; qp[0] = 1.0f;
#pragma unroll
    for (int k = 1; k < 16; ++k) {
        yp[k] = yp[k - 1] * y;
        qp[k] = qp[k - 1] * q;
    }

    float U[16];
#pragma unroll
    for (int m = 0; m < 16; ++m)
        U[m] = K[m] * yp[m] * qp[15 - m];

    o[0] = -U[0];
#pragma unroll
    for (int m = 1; m < 16; ++m)
        o[m] = U[m - 1] - U[m];
    o[16] = U[15];

    if (y == 0.0f) { o[0]  = 0.0f; o[1]  = 0.0f; }
    if (y == 1.0f) { o[15] = 0.0f; o[16] = 0.0f; }
}

__global__ __launch_bounds__(TPB)
void evalbspprime_kernel(const float* __restrict__ x,
                         float* __restrict__ out,
                         int n)
{
    __shared__ __align__(128) float s[TILE_WORDS];   // 8704 B

    const int tid  = threadIdx.x;
    const int base = blockIdx.x * TPB;
    const int idx  = base + tid;

    // L2 prefetch for the CTA ~one wave ahead: 128 floats = 4 x 128B lines.
    if (tid < 4) {
        const int pf = base + AHEAD * TPB + tid * 32;
        if (pf < n)
            asm volatile("prefetch.global.L2 [%0];" :: "l"(x + pf));
    }

    float y = (idx < n) ? x[idx] : 0.5f;
    float o[NCOL];
    compute_point(y, o);

    // stride-17 words per thread: 17 coprime to 32 banks -> conflict-free
#pragma unroll
    for (int m = 0; m < NCOL; ++m)
        s[tid * NCOL + m] = o[m];

    __syncthreads();

    if (base + TPB <= n) {
        if (tid == 0) {
            asm volatile("fence.proxy.async.shared::cta;" ::: "memory");
            uint32_t saddr = (uint32_t)__cvta_generic_to_shared(s);
            const float* g = out + (long long)base * NCOL;
            uint64_t pol;
            asm volatile("createpolicy.fractional.L2::evict_first.b64 %0, 1.0;"
                         : "=l"(pol));
            asm volatile(
                "cp.async.bulk.global.shared::cta.bulk_group.L2::cache_hint "
                "[%0], [%1], %2, %3;"
                :: "l"(g), "r"(saddr), "n"(TILE_BYTES), "l"(pol) : "memory");
            asm volatile("cp.async.bulk.commit_group;" ::: "memory");
            // drain before CTA exit (smem dealloc safety)
            asm volatile("cp.async.bulk.wait_group.read 0;" ::: "memory");
        }
    } else {
        // tail (absent for n = 4,000,000): coalesced scalar fallback
        const long long obase = (long long)base * NCOL;
        const int rem = (n - base) * NCOL;
        for (int i = tid; i < rem; i += TPB)
            out[obase + i] = s[i];
    }
}

extern "C" void kernel_launch(void* const* d_in, const int* in_sizes, int n_in,
                              void* d_out, int out_size)
{
    const float* x = (const float*)d_in[0];
    float* out = (float*)d_out;
    const int n = in_sizes[0];          // 4,000,000
    const int blocks = (n + TPB - 1) / TPB;   // 31250
    evalbspprime_kernel<<<blocks, TPB>>>(x, out, n);
}

// round 7
// speedup vs baseline: 1.2668x; 1.2668x over previous
#include <cuda_runtime.h>
#include <cstdint>

// EvalBspPrimeTF: derivative of Bernstein basis, order 16, 4M points -> [4M,17] f32.
// Telescoping form: U_m = 16*C(15,m)*y^m*(1-y)^(15-m), m=0..15
//   out[0] = -U_0;  out[m] = U_{m-1} - U_m (1<=m<=15);  out[16] = U_15
// Reference NaN->0: at y==0, out[0]=out[1]=0; at y==1, out[15]=out[16]=0.
//
// R7: TPB=128, 256 points per CTA, two half-tile (8704B) TMA bulk stores.
// Compute of half B overlaps the drain of half A; both x loads issued up
// front (MLP=2). No cache hints (R6 showed they poison the store path).

#define TPB   128
#define NCOL  17
#define PTS_PER_CTA  256
#define HALF_WORDS (TPB * NCOL)           // 2176 floats
#define HALF_BYTES (HALF_WORDS * 4)       // 8704 B, multiple of 16

__device__ __forceinline__ void compute_point(float y, float* __restrict__ o)
{
    // 16*C(15,m)
    const float K[16] = {
        16.f, 240.f, 1680.f, 7280.f, 21840.f, 48048.f, 80080.f, 102960.f,
        102960.f, 80080.f, 48048.f, 21840.f, 7280.f, 1680.f, 240.f, 16.f
    };
    float q = 1.0f - y;

    float yp[16], qp[16];
    yp[0] = 1.0f; qp[0] = 1.0f;
#pragma unroll
    for (int k = 1; k < 16; ++k) {
        yp[k] = yp[k - 1] * y;
        qp[k] = qp[k - 1] * q;
    }

    float U[16];
#pragma unroll
    for (int m = 0; m < 16; ++m)
        U[m] = K[m] * yp[m] * qp[15 - m];

    o[0] = -U[0];
#pragma unroll
    for (int m = 1; m < 16; ++m)
        o[m] = U[m - 1] - U[m];
    o[16] = U[15];

    if (y == 0.0f) { o[0]  = 0.0f; o[1]  = 0.0f; }
    if (y == 1.0f) { o[15] = 0.0f; o[16] = 0.0f; }
}

__device__ __forceinline__ void bulk_store(const float* g, const float* sbuf)
{
    asm volatile("fence.proxy.async.shared::cta;" ::: "memory");
    uint32_t saddr = (uint32_t)__cvta_generic_to_shared(sbuf);
    asm volatile(
        "cp.async.bulk.global.shared::cta.bulk_group [%0], [%1], %2;"
        :: "l"(g), "r"(saddr), "n"(HALF_BYTES) : "memory");
    asm volatile("cp.async.bulk.commit_group;" ::: "memory");
}

__global__ __launch_bounds__(TPB)
void evalbspprime_kernel(const float* __restrict__ x,
                         float* __restrict__ out,
                         int n)
{
    __shared__ __align__(128) float sA[HALF_WORDS];   // 8704 B
    __shared__ __align__(128) float sB[HALF_WORDS];   // 8704 B

    const int tid   = threadIdx.x;
    const int base  = blockIdx.x * PTS_PER_CTA;
    const int idxA  = base + tid;
    const int idxB  = base + TPB + tid;

    if (base + PTS_PER_CTA <= n) {
        // both loads issued back-to-back: MLP=2, one exposed DRAM latency
        float yA = x[idxA];
        float yB = x[idxB];

        // ---- half A ----
        float o[NCOL];
        compute_point(yA, o);
#pragma unroll
        for (int m = 0; m < NCOL; ++m)
            sA[tid * NCOL + m] = o[m];          // stride 17: conflict-free
        __syncthreads();
        if (tid == 0)
            bulk_store(out + (long long)base * NCOL, sA);

        // ---- half B (overlaps A's drain) ----
        compute_point(yB, o);
#pragma unroll
        for (int m = 0; m < NCOL; ++m)
            sB[tid * NCOL + m] = o[m];
        __syncthreads();
        if (tid == 0) {
            bulk_store(out + (long long)(base + TPB) * NCOL, sB);
            // drain both before CTA exit (smem dealloc safety)
            asm volatile("cp.async.bulk.wait_group.read 0;" ::: "memory");
        }
    } else {
        // tail (absent for n = 4,000,000): scalar coalesced fallback
        for (int h = 0; h < 2; ++h) {
            const int b = base + h * TPB;
            const int i = b + tid;
            float* sbuf = h ? sB : sA;
            float y = (i < n) ? x[i] : 0.5f;
            float o[NCOL];
            compute_point(y, o);
#pragma unroll
            for (int m = 0; m < NCOL; ++m)
                sbuf[tid * NCOL + m] = o[m];
            __syncthreads();
            if (b < n) {
                const long long obase = (long long)b * NCOL;
                const int rem = min(TPB, n - b) * NCOL;
                for (int k = tid; k < rem; k += TPB)
                    out[obase + k] = sbuf[k];
            }
            __syncthreads();
        }
    }
}

extern "C" void kernel_launch(void* const* d_in, const int* in_sizes, int n_in,
                              void* d_out, int out_size)
{
    const float* x = (const float*)d_in[0];
    float* out = (float*)d_out;
    const int n = in_sizes[0];          // 4,000,000
    const int blocks = (n + PTS_PER_CTA - 1) / PTS_PER_CTA;   // 15625
    evalbspprime_kernel<<<blocks, TPB>>>(x, out, n);
}